// round 6
// baseline (speedup 1.0000x reference)
#include <cuda_runtime.h>

// Problem dims (fixed by the dataset)
constexpr int L = 13;
constexpr int B = 16;
constexpr int S = 512;
constexpr int D = 768;
constexpr int W = 256;
constexpr int D4 = D / 4;          // 192 float4 per output row

// One block per output row (l,b,w); 192 threads, one float4 column each.
// Grid = L*B*W = 53248 blocks.
__global__ void __launch_bounds__(D4) segment_sum_block(
    const float4* __restrict__ hidden,   // [L,B,S,D4]
    const int*    __restrict__ seg,      // [B,S] sorted per row
    float4*       __restrict__ out       // [L,B,W,D4]
) {
    const int row = blockIdx.x;          // l*B*W + b*W + w
    const int w   = row % W;
    const int bl  = row / W;             // l*B + b
    const int b   = bl % B;

    __shared__ int s_span[2];            // [s0, s1]

    // Lanes 0 and 1 of warp 0 each run one lower_bound over the sorted row.
    if (threadIdx.x < 2) {
        const int* srow = seg + b * S;
        const int target = w + threadIdx.x;      // lane0: w, lane1: w+1
        int lo = 0, hi = S;
        while (lo < hi) {
            int mid = (lo + hi) >> 1;
            if (__ldg(srow + mid) < target) lo = mid + 1; else hi = mid;
        }
        s_span[threadIdx.x] = lo;
    }
    __syncthreads();

    const int s0 = s_span[0];
    const int s1 = s_span[1];

    const float4* src = hidden + ((long long)bl * S + s0) * D4 + threadIdx.x;
    float4 acc0 = make_float4(0.f, 0.f, 0.f, 0.f);
    float4 acc1 = make_float4(0.f, 0.f, 0.f, 0.f);

    // Unroll by 2 over s: two independent loads in flight per thread.
    int s = s0;
    for (; s + 1 < s1; s += 2) {
        float4 v0 = __ldg(src);
        float4 v1 = __ldg(src + D4);
        acc0.x += v0.x; acc0.y += v0.y; acc0.z += v0.z; acc0.w += v0.w;
        acc1.x += v1.x; acc1.y += v1.y; acc1.z += v1.z; acc1.w += v1.w;
        src += 2 * D4;
    }
    if (s < s1) {
        float4 v0 = __ldg(src);
        acc0.x += v0.x; acc0.y += v0.y; acc0.z += v0.z; acc0.w += v0.w;
    }
    acc0.x += acc1.x; acc0.y += acc1.y; acc0.z += acc1.z; acc0.w += acc1.w;

    out[(long long)row * D4 + threadIdx.x] = acc0;
}

extern "C" void kernel_launch(void* const* d_in, const int* in_sizes, int n_in,
                              void* d_out, int out_size) {
    const float* hidden = (const float*)d_in[0];
    const int*   seg    = (const int*)d_in[1];
    // d_in[2] = num_words scalar — W hardcoded.

    int blocks = L * B * W;              // 53248
    segment_sum_block<<<blocks, D4>>>(
        (const float4*)hidden, seg, (float4*)d_out);
}

// round 7
// speedup vs baseline: 1.0655x; 1.0655x over previous
#include <cuda_runtime.h>

// Problem dims (fixed by the dataset)
constexpr int L = 13;
constexpr int B = 16;
constexpr int S = 512;
constexpr int D = 768;
constexpr int W = 256;
constexpr int D4 = D / 4;                 // 192 float4 per row
constexpr int NT = B * W * D4;            // threads per layer-group = 786432
constexpr int LG0 = 7;                    // layers in group 0
// group 1 has L - LG0 = 6 layers

// One thread per (b, w, c, layer-group). Search once, stream 6-7 layers with
// independent loads per s-iteration (MLP ~= nl).
__global__ void __launch_bounds__(256) segment_sum_layers(
    const float4* __restrict__ hidden,    // [L,B,S,D4]
    const int*    __restrict__ seg,       // [B,S] sorted per row
    float4*       __restrict__ out        // [L,B,W,D4]
) {
    int idx = blockIdx.x * blockDim.x + threadIdx.x;   // [0, 2*NT)
    int g   = idx / NT;                   // layer group 0/1
    int r   = idx % NT;
    int c   = r % D4;
    int w   = (r / D4) % W;
    int b   = r / (D4 * W);

    const int l0 = g * LG0;               // 0 or 7
    const int nl = g ? (L - LG0) : LG0;   // 7 or 6

    // Span via two lower_bounds; warp-uniform (all lanes share b,w) ->
    // broadcast L1 loads, cost amortized over nl layers of streaming.
    const int* srow = seg + b * S;
    int s0, s1;
    {
        int lo = 0, hi = S;
        while (lo < hi) {
            int mid = (lo + hi) >> 1;
            if (__ldg(srow + mid) < w) lo = mid + 1; else hi = mid;
        }
        s0 = lo;
        int w1 = w + 1;
        lo = s0; hi = S;
        while (lo < hi) {
            int mid = (lo + hi) >> 1;
            if (__ldg(srow + mid) < w1) lo = mid + 1; else hi = mid;
        }
        s1 = lo;
    }

    float4 acc[LG0];
    #pragma unroll
    for (int l = 0; l < LG0; ++l) acc[l] = make_float4(0.f, 0.f, 0.f, 0.f);

    // Base pointer for layer l0, sentence b, token s0, column c.
    const float4* src = hidden + (((long long)l0 * B + b) * S + s0) * D4 + c;
    constexpr long long LSTRIDE = (long long)B * S * D4;   // float4s per layer

    for (int s = s0; s < s1; ++s) {
        #pragma unroll
        for (int l = 0; l < LG0; ++l) {
            if (l < nl) {
                float4 v = __ldg(src + l * LSTRIDE);
                acc[l].x += v.x; acc[l].y += v.y;
                acc[l].z += v.z; acc[l].w += v.w;
            }
        }
        src += D4;
    }

    float4* dst = out + (((long long)l0 * B + b) * W + w) * D4 + c;
    constexpr long long OSTRIDE = (long long)B * W * D4;
    #pragma unroll
    for (int l = 0; l < LG0; ++l) {
        if (l < nl) dst[l * OSTRIDE] = acc[l];
    }
}

extern "C" void kernel_launch(void* const* d_in, const int* in_sizes, int n_in,
                              void* d_out, int out_size) {
    const float* hidden = (const float*)d_in[0];
    const int*   seg    = (const int*)d_in[1];
    // d_in[2] = num_words scalar — W hardcoded.

    int total  = 2 * NT;                  // 1,572,864 (divisible by 256)
    int blocks = total / 256;             // 6144
    segment_sum_layers<<<blocks, 256>>>(
        (const float4*)hidden, seg, (float4*)d_out);
}

// round 8
// speedup vs baseline: 1.1241x; 1.0550x over previous
#include <cuda_runtime.h>

// Problem dims (fixed by the dataset)
constexpr int L = 13;
constexpr int B = 16;
constexpr int S = 512;
constexpr int D = 768;
constexpr int W = 256;
constexpr int D4 = D / 4;          // 192 float4 per row

// One thread per output float4 (R2 layout), fused span lookup.
// Lanes 0/1 of each warp search lower_bound(w) / lower_bound(w+1) in parallel
// (one ~10-step L1 pointer chase instead of two), then shfl-broadcast.
__global__ void __launch_bounds__(256) segment_sum_fused(
    const float4* __restrict__ hidden,   // [L,B,S,D4]
    const int*    __restrict__ seg,      // [B,S] sorted per row
    float4*       __restrict__ out       // [L,B,W,D4]
) {
    int idx = blockIdx.x * blockDim.x + threadIdx.x;   // output float4 index
    int d4  = idx % D4;
    int row = idx / D4;            // l*B*W + b*W + w
    int w   = row % W;
    int bl  = row / W;             // l*B + b
    int b   = bl % B;

    // Paired warp search: all 32 lanes share (b,w); even lanes target w,
    // odd lanes target w+1. One dependent-load chain serves both bounds.
    const int* srow = seg + b * S;
    int target = w + (threadIdx.x & 1);
    int lo = 0, hi = S;
    while (lo < hi) {
        int mid = (lo + hi) >> 1;
        if (__ldg(srow + mid) < target) lo = mid + 1; else hi = mid;
    }
    const unsigned m = 0xFFFFFFFFu;
    int s0 = __shfl_sync(m, lo, 0);
    int s1 = __shfl_sync(m, lo, 1);

    const float4* src = hidden + ((long long)bl * S + s0) * D4 + d4;
    float4 acc0 = make_float4(0.f, 0.f, 0.f, 0.f);
    float4 acc1 = make_float4(0.f, 0.f, 0.f, 0.f);

    int s = s0;
    for (; s + 1 < s1; s += 2) {
        float4 v0 = __ldcs(src);
        float4 v1 = __ldcs(src + D4);
        acc0.x += v0.x; acc0.y += v0.y; acc0.z += v0.z; acc0.w += v0.w;
        acc1.x += v1.x; acc1.y += v1.y; acc1.z += v1.z; acc1.w += v1.w;
        src += 2 * D4;
    }
    if (s < s1) {
        float4 v0 = __ldcs(src);
        acc0.x += v0.x; acc0.y += v0.y; acc0.z += v0.z; acc0.w += v0.w;
    }
    acc0.x += acc1.x; acc0.y += acc1.y; acc0.z += acc1.z; acc0.w += acc1.w;

    __stcs(out + idx, acc0);       // streaming store, evict-first
}

extern "C" void kernel_launch(void* const* d_in, const int* in_sizes, int n_in,
                              void* d_out, int out_size) {
    const float* hidden = (const float*)d_in[0];
    const int*   seg    = (const int*)d_in[1];
    // d_in[2] = num_words scalar — W hardcoded.

    long long total = (long long)L * B * W * D4;   // 10,223,616
    int threads = 256;
    int blocks = (int)(total / threads);           // 39936 exactly
    segment_sum_fused<<<blocks, threads>>>(
        (const float4*)hidden, seg, (float4*)d_out);
}

// round 9
// speedup vs baseline: 1.2396x; 1.1027x over previous
#include <cuda_runtime.h>

// Problem dims (fixed by the dataset)
constexpr int L = 13;
constexpr int B = 16;
constexpr int S = 512;
constexpr int D = 768;
constexpr int W = 256;
constexpr int D4 = D / 4;          // 192 float4 per row

// One thread per output float4 (proven-best R2 layout), single launch.
// Span lookup via warp-cooperative 32-ary search: 2 dependent L1 loads total
// (vs ~19 for two scalar binary searches). All lanes of a warp share (b,w).
__global__ void __launch_bounds__(256) segment_sum_warp(
    const float4* __restrict__ hidden,   // [L,B,S,D4]
    const int*    __restrict__ seg,      // [B,S] sorted per row
    float4*       __restrict__ out       // [L,B,W,D4]
) {
    int idx = blockIdx.x * blockDim.x + threadIdx.x;   // output float4 index
    int d4  = idx % D4;
    int row = idx / D4;            // l*B*W + b*W + w
    int w   = row % W;
    int bl  = row / W;             // l*B + b
    int b   = bl % B;

    const int* srow = seg + b * S;
    const int lane = threadIdx.x & 31;

    // Round 1: probe positions 0,16,...,496. Two ballots bracket both bounds.
    int v1 = __ldg(srow + lane * 16);
    unsigned m0 = __ballot_sync(0xFFFFFFFFu, v1 < w);        // for lower_bound(w)
    unsigned m1 = __ballot_sync(0xFFFFFFFFu, v1 <= w);       // for lower_bound(w+1)
    int c0 = __popc(m0), c1 = __popc(m1);
    int base0 = c0 ? (c0 - 1) * 16 + 1 : 0;
    int base1 = c1 ? (c1 - 1) * 16 + 1 : 0;

    // Round 2: lanes 0-15 refine lower_bound(w), lanes 16-31 lower_bound(w+1).
    int sub  = lane & 15;
    int base = (lane < 16) ? base0 : base1;
    int tgt  = (lane < 16) ? w : (w + 1);
    int pos  = base + sub;
    int v2   = (pos < S) ? __ldg(srow + pos) : 0x7fffffff;
    unsigned m2 = __ballot_sync(0xFFFFFFFFu, v2 < tgt);
    int s0 = base0 + __popc(m2 & 0xFFFFu);
    int s1 = base1 + __popc(m2 >> 16);

    // Streaming body — identical to the best-measured R2 kernel.
    const float4* src = hidden + ((long long)bl * S + s0) * D4 + d4;
    float4 acc = make_float4(0.f, 0.f, 0.f, 0.f);
    for (int s = s0; s < s1; ++s) {
        float4 v = *src;
        acc.x += v.x; acc.y += v.y; acc.z += v.z; acc.w += v.w;
        src += D4;
    }
    out[idx] = acc;
}

extern "C" void kernel_launch(void* const* d_in, const int* in_sizes, int n_in,
                              void* d_out, int out_size) {
    const float* hidden = (const float*)d_in[0];
    const int*   seg    = (const int*)d_in[1];
    // d_in[2] = num_words scalar — W hardcoded.

    long long total = (long long)L * B * W * D4;   // 10,223,616
    int threads = 256;
    int blocks = (int)(total / threads);           // 39936 exactly
    segment_sum_warp<<<blocks, threads>>>(
        (const float4*)hidden, seg, (float4*)d_out);
}

// round 10
// speedup vs baseline: 1.2694x; 1.0241x over previous
#include <cuda_runtime.h>

// Problem dims (fixed by the dataset)
constexpr int L = 13;
constexpr int B = 16;
constexpr int S = 512;
constexpr int D = 768;
constexpr int W = 256;
constexpr int D4 = D / 4;          // 192 float4 per row

// Scratch: starts[b][w] = first s with seg[b,s] >= w; starts[b][W] = S.
__device__ int g_starts[B * (W + 1)];

// Kernel A: one block per sentence. Stage the 2KB seg row into smem with ONE
// coalesced parallel load, then 257 threads binary-search smem (9 x LDS ~=
// 260 cycles) instead of chasing 10 dependent cold-DRAM loads (~6000 cycles).
__global__ void __launch_bounds__(S) compute_starts_kernel(const int* __restrict__ seg) {
    __shared__ int s_seg[S];
    const int b = blockIdx.x;
    s_seg[threadIdx.x] = seg[b * S + threadIdx.x];
    __syncthreads();

    int w = threadIdx.x;
    if (w <= W) {
        int lo = 0, hi = S;
        while (lo < hi) {
            int mid = (lo + hi) >> 1;
            if (s_seg[mid] < w) lo = mid + 1; else hi = mid;
        }
        g_starts[b * (W + 1) + w] = lo;
    }
}

// Kernel B: proven-best streaming body (R2, 77.6us, DRAM 75.2%).
// One thread per output float4; warps never cross rows (192 % 32 == 0).
__global__ void __launch_bounds__(256) segment_sum_kernel(
    const float4* __restrict__ hidden,   // [L,B,S,D4]
    float4* __restrict__ out             // [L,B,W,D4]
) {
    int idx = blockIdx.x * blockDim.x + threadIdx.x;   // output float4 index
    int d4 = idx % D4;
    int w_lin = idx / D4;          // l*B*W + b*W + w
    int w = w_lin % W;
    int bl = w_lin / W;            // l*B + b
    int b = bl % B;

    int s0 = g_starts[b * (W + 1) + w];
    int s1 = g_starts[b * (W + 1) + w + 1];

    const float4* src = hidden + ((long long)bl * S + s0) * D4 + d4;
    float4 acc = make_float4(0.f, 0.f, 0.f, 0.f);
    for (int s = s0; s < s1; ++s) {
        float4 v = *src;
        acc.x += v.x; acc.y += v.y; acc.z += v.z; acc.w += v.w;
        src += D4;
    }
    out[idx] = acc;
}

extern "C" void kernel_launch(void* const* d_in, const int* in_sizes, int n_in,
                              void* d_out, int out_size) {
    const float* hidden = (const float*)d_in[0];
    const int*   seg    = (const int*)d_in[1];
    // d_in[2] = num_words scalar — W hardcoded.

    compute_starts_kernel<<<B, S>>>(seg);

    long long total = (long long)L * B * W * D4;   // 10,223,616
    int threads = 256;
    int blocks = (int)(total / threads);           // 39936 exactly
    segment_sum_kernel<<<blocks, threads>>>(
        (const float4*)hidden, (float4*)d_out);
}